// round 5
// baseline (speedup 1.0000x reference)
#include <cuda_runtime.h>
#include <math.h>

// Shapes
#define BATCH 512
#define SIG   512
#define HID   1024
#define EDGE  512
#define SLOTS 256
#define MEM   512
#define IOC   256
#define GRP   32
#define CATK  (EDGE + GRP)   // 544

// ---------------- scratch (single __device__ symbol, offsets in floats) ----
#define OFF_LAT1   0
#define OFF_READY  524288
#define OFF_QUERY  786432
#define OFF_LOGITS 1048576
#define OFF_VALUE  1179648
#define OFF_READ   1441792
#define OFF_GATE   1703936
#define OFF_CAT    1704448
#define OFF_H      1982976
#define OFF_ADAPT  2245120
#define OFF_UV     2507264
#define OFF_P      3031552
#define OFF_R      3162624
#define SCRATCH_FLOATS 3424768

__device__ float g_scratch[SCRATCH_FLOATS];

// Output layout (flat concat, reference return order)
#define OUT_LATENT  0
#define OUT_REFINED 524288
#define OUT_ENERGY  786432
#define OUT_IO      786944
#define OUT_NEWMEM  918016
#define OUT_WEIGHTS 68026880

// ---------------------------------------------------------------------------
__device__ __forceinline__ float sigmoidf_(float x) { return 1.0f / (1.0f + expf(-x)); }
__device__ __forceinline__ float siluf_(float x)    { return x / (1.0f + expf(-x)); }

__device__ __forceinline__ float blockReduceSum(float v) {
    __shared__ float sh[33];
    __syncthreads();
    int lane = threadIdx.x & 31, wid = threadIdx.x >> 5;
    #pragma unroll
    for (int o = 16; o > 0; o >>= 1) v += __shfl_down_sync(0xffffffffu, v, o);
    if (lane == 0) sh[wid] = v;
    __syncthreads();
    int nw = (blockDim.x + 31) >> 5;
    if (wid == 0) {
        float w = (lane < nw) ? sh[lane] : 0.0f;
        #pragma unroll
        for (int o = 16; o > 0; o >>= 1) w += __shfl_down_sync(0xffffffffu, w, o);
        if (lane == 0) sh[32] = w;
    }
    __syncthreads();
    return sh[32];
}

__device__ __forceinline__ float blockReduceMax(float v) {
    __shared__ float sh[33];
    __syncthreads();
    int lane = threadIdx.x & 31, wid = threadIdx.x >> 5;
    #pragma unroll
    for (int o = 16; o > 0; o >>= 1) v = fmaxf(v, __shfl_down_sync(0xffffffffu, v, o));
    if (lane == 0) sh[wid] = v;
    __syncthreads();
    int nw = (blockDim.x + 31) >> 5;
    if (wid == 0) {
        float w = (lane < nw) ? sh[lane] : -3.4e38f;
        #pragma unroll
        for (int o = 16; o > 0; o >>= 1) w = fmaxf(w, __shfl_down_sync(0xffffffffu, w, o));
        if (lane == 0) sh[32] = w;
    }
    __syncthreads();
    return sh[32];
}

// ---------------------------------------------------------------------------
// 3xTF32 tensor-core GEMM: C[M,N] = act(A[M,K] @ W[N,K]^T + bias + addend)
// BM=BN=64, BK=16, 128 threads (4 warps, each 32x32 via 2x4 m16n8k8 atoms).
// fp32 accuracy via hi/lo tf32 split: hi*hi + hi*lo + lo*hi.
// Requires M,N mult of 64, K mult of 16, rows 16B-aligned.
__device__ __forceinline__ unsigned f2tf32(float f) {
    unsigned u;
    asm("cvt.rna.tf32.f32 %0, %1;" : "=r"(u) : "f"(f));
    return u;
}

__device__ __forceinline__ void mma_tf32(float c[4], const unsigned a[4], const unsigned b[2]) {
    asm volatile(
        "mma.sync.aligned.m16n8k8.row.col.f32.tf32.tf32.f32 "
        "{%0,%1,%2,%3}, {%4,%5,%6,%7}, {%8,%9}, {%0,%1,%2,%3};\n"
        : "+f"(c[0]), "+f"(c[1]), "+f"(c[2]), "+f"(c[3])
        : "r"(a[0]), "r"(a[1]), "r"(a[2]), "r"(a[3]), "r"(b[0]), "r"(b[1]));
}

#define SMPITCH 20   // bank-conflict-free pitch for fragment loads

template<int ACT>
__global__ void gemm_tf32_kernel(const float* __restrict__ A,
                                 const float* __restrict__ W,
                                 const float* __restrict__ bias,
                                 const float* __restrict__ addend,
                                 float* __restrict__ C,
                                 int M, int N, int K) {
    __shared__ float Ah[64][SMPITCH];
    __shared__ float Al[64][SMPITCH];
    __shared__ float Bh[64][SMPITCH];
    __shared__ float Bl[64][SMPITCH];

    const int bx = blockIdx.x;           // N tile
    const int by = blockIdx.y;           // M tile
    const int tid = threadIdx.x;
    const int lane = tid & 31;
    const int warp = tid >> 5;
    const int wm = (warp >> 1) << 5;     // 0 or 32
    const int wn = (warp & 1) << 5;      // 0 or 32

    // tile-load mapping: thread owns 8 consecutive k of one row (2x float4)
    const int trow = tid >> 1;           // 0..63
    const int tkof = (tid & 1) << 3;     // 0 or 8

    const float* Aptr = A + (size_t)(by * 64 + trow) * K + tkof;
    const float* Wptr = W + (size_t)(bx * 64 + trow) * K + tkof;

    float c[2][4][4];
    #pragma unroll
    for (int mi = 0; mi < 2; mi++)
        #pragma unroll
        for (int ni = 0; ni < 4; ni++)
            #pragma unroll
            for (int r = 0; r < 4; r++) c[mi][ni][r] = 0.0f;

    float4 av0 = *reinterpret_cast<const float4*>(Aptr);
    float4 av1 = *reinterpret_cast<const float4*>(Aptr + 4);
    float4 wv0 = *reinterpret_cast<const float4*>(Wptr);
    float4 wv1 = *reinterpret_cast<const float4*>(Wptr + 4);

    const int r4 = lane >> 2;            // 0..7
    const int c4 = lane & 3;             // 0..3

    for (int kt = 0; kt < K; kt += 16) {
        // convert + stage current tile
        {
            float va[8] = {av0.x, av0.y, av0.z, av0.w, av1.x, av1.y, av1.z, av1.w};
            float vw[8] = {wv0.x, wv0.y, wv0.z, wv0.w, wv1.x, wv1.y, wv1.z, wv1.w};
            #pragma unroll
            for (int i = 0; i < 8; i++) {
                unsigned ahu = f2tf32(va[i]);
                float ahf = __uint_as_float(ahu);
                Ah[trow][tkof + i] = ahf;
                Al[trow][tkof + i] = __uint_as_float(f2tf32(va[i] - ahf));
                unsigned bhu = f2tf32(vw[i]);
                float bhf = __uint_as_float(bhu);
                Bh[trow][tkof + i] = bhf;
                Bl[trow][tkof + i] = __uint_as_float(f2tf32(vw[i] - bhf));
            }
        }
        __syncthreads();

        if (kt + 16 < K) {               // prefetch next tile
            av0 = *reinterpret_cast<const float4*>(Aptr + kt + 16);
            av1 = *reinterpret_cast<const float4*>(Aptr + kt + 20);
            wv0 = *reinterpret_cast<const float4*>(Wptr + kt + 16);
            wv1 = *reinterpret_cast<const float4*>(Wptr + kt + 20);
        }

        #pragma unroll
        for (int ks = 0; ks < 16; ks += 8) {
            unsigned ah[2][4], al[2][4], bh[4][2], bl[4][2];
            #pragma unroll
            for (int mi = 0; mi < 2; mi++) {
                int mb = wm + mi * 16;
                ah[mi][0] = __float_as_uint(Ah[mb + r4    ][ks + c4    ]);
                ah[mi][1] = __float_as_uint(Ah[mb + r4 + 8][ks + c4    ]);
                ah[mi][2] = __float_as_uint(Ah[mb + r4    ][ks + c4 + 4]);
                ah[mi][3] = __float_as_uint(Ah[mb + r4 + 8][ks + c4 + 4]);
                al[mi][0] = __float_as_uint(Al[mb + r4    ][ks + c4    ]);
                al[mi][1] = __float_as_uint(Al[mb + r4 + 8][ks + c4    ]);
                al[mi][2] = __float_as_uint(Al[mb + r4    ][ks + c4 + 4]);
                al[mi][3] = __float_as_uint(Al[mb + r4 + 8][ks + c4 + 4]);
            }
            #pragma unroll
            for (int ni = 0; ni < 4; ni++) {
                int nb = wn + ni * 8 + r4;
                bh[ni][0] = __float_as_uint(Bh[nb][ks + c4    ]);
                bh[ni][1] = __float_as_uint(Bh[nb][ks + c4 + 4]);
                bl[ni][0] = __float_as_uint(Bl[nb][ks + c4    ]);
                bl[ni][1] = __float_as_uint(Bl[nb][ks + c4 + 4]);
            }
            #pragma unroll
            for (int mi = 0; mi < 2; mi++)
                #pragma unroll
                for (int ni = 0; ni < 4; ni++) {
                    mma_tf32(c[mi][ni], ah[mi], bh[ni]);
                    mma_tf32(c[mi][ni], ah[mi], bl[ni]);
                    mma_tf32(c[mi][ni], al[mi], bh[ni]);
                }
        }
        __syncthreads();
    }

    // epilogue: bias + addend + activation, fp32 write
    #pragma unroll
    for (int mi = 0; mi < 2; mi++) {
        #pragma unroll
        for (int ni = 0; ni < 4; ni++) {
            int col0 = bx * 64 + wn + ni * 8 + c4 * 2;
            #pragma unroll
            for (int half = 0; half < 2; half++) {    // c0/c1 then c2/c3
                int row = by * 64 + wm + mi * 16 + r4 + half * 8;
                float v0 = c[mi][ni][half * 2 + 0];
                float v1 = c[mi][ni][half * 2 + 1];
                if (bias)   { v0 += bias[col0]; v1 += bias[col0 + 1]; }
                if (addend) {
                    const float* ad = addend + (size_t)row * N + col0;
                    v0 += ad[0]; v1 += ad[1];
                }
                if (ACT == 1) { v0 = siluf_(v0); v1 = siluf_(v1); }
                if (ACT == 2) { v0 = sigmoidf_(v0); v1 = sigmoidf_(v1); }
                *reinterpret_cast<float2*>(C + (size_t)row * N + col0) = make_float2(v0, v1);
            }
        }
    }
}

// ---------------------------------------------------------------------------
// energy[b] = relu(dot(latent[b,:], ew) + eb)
__global__ void energy_kernel(const float* __restrict__ latent,
                              const float* __restrict__ ew,
                              const float* __restrict__ eb,
                              float* __restrict__ out) {
    int b = blockIdx.x;
    const float4* x = reinterpret_cast<const float4*>(latent + (size_t)b * HID);
    const float4* w = reinterpret_cast<const float4*>(ew);
    float s = 0.0f;
    for (int i = threadIdx.x; i < HID / 4; i += blockDim.x) {
        float4 xv = x[i], wv = w[i];
        s += xv.x * wv.x + xv.y * wv.y + xv.z * wv.z + xv.w * wv.w;
    }
    s = blockReduceSum(s);
    if (threadIdx.x == 0) out[b] = fmaxf(s + eb[0], 0.0f);
}

// softmax over 256 cols (one block of 256 threads per row)
__global__ void softmax256_kernel(const float* __restrict__ logits,
                                  float* __restrict__ wout) {
    int b = blockIdx.x;
    float x = logits[(size_t)b * SLOTS + threadIdx.x];
    float m = blockReduceMax(x);
    float e = expf(x - m);
    float s = blockReduceSum(e);
    wout[(size_t)b * SLOTS + threadIdx.x] = e / s;
}

// read[b,d] = sum_s weights[b,s] * memory[b,s,d]
__global__ void read_kernel(const float* __restrict__ weights,
                            const float* __restrict__ memory,
                            float* __restrict__ readv) {
    int b = blockIdx.x;
    __shared__ float w[SLOTS];
    for (int i = threadIdx.x; i < SLOTS; i += blockDim.x)
        w[i] = weights[(size_t)b * SLOTS + i];
    __syncthreads();
    int d4 = threadIdx.x;  // 128 threads, float4 index
    const float4* mb = reinterpret_cast<const float4*>(memory + (size_t)b * SLOTS * MEM);
    float4 acc = make_float4(0.f, 0.f, 0.f, 0.f);
    #pragma unroll 4
    for (int s = 0; s < SLOTS; s++) {
        float ws = w[s];
        float4 m = mb[(size_t)s * (MEM / 4) + d4];
        acc.x = fmaf(ws, m.x, acc.x);
        acc.y = fmaf(ws, m.y, acc.y);
        acc.z = fmaf(ws, m.z, acc.z);
        acc.w = fmaf(ws, m.w, acc.w);
    }
    reinterpret_cast<float4*>(readv + (size_t)b * MEM)[d4] = acc;
}

// gate[b] = sigmoid(latent[b]·wg[0:HID] + read[b]·wg[HID:HID+MEM] + wgb)
__global__ void gate_kernel(const float* __restrict__ latent,
                            const float* __restrict__ readv,
                            const float* __restrict__ wg,
                            const float* __restrict__ wgb,
                            float* __restrict__ gate) {
    int b = blockIdx.x;
    float s = 0.0f;
    for (int i = threadIdx.x; i < HID; i += blockDim.x)
        s += latent[(size_t)b * HID + i] * wg[i];
    for (int i = threadIdx.x; i < MEM; i += blockDim.x)
        s += readv[(size_t)b * MEM + i] * wg[HID + i];
    s = blockReduceSum(s);
    if (threadIdx.x == 0) gate[b] = sigmoidf_(s + wgb[0]);
}

// new_memory[b,s,d] = m + gate[b]*w[b,s]*(value[b,d] - m), float4 over d
__global__ void newmem_kernel(const float* __restrict__ memory,
                              const float* __restrict__ weights,
                              const float* __restrict__ gate,
                              const float* __restrict__ value,
                              float* __restrict__ out) {
    size_t idx = (size_t)blockIdx.x * blockDim.x + threadIdx.x;  // float4 index
    int b   = (int)(idx >> 15);           // SLOTS*MEM/4 = 32768 per batch
    int rem = (int)(idx & 32767);
    int s   = rem >> 7;                   // MEM/4 = 128
    int d4  = rem & 127;
    float gw = gate[b] * weights[(size_t)b * SLOTS + s];
    float4 m = reinterpret_cast<const float4*>(memory)[idx];
    float4 v = reinterpret_cast<const float4*>(value)[(size_t)b * 128 + d4];
    float4 o;
    o.x = fmaf(gw, v.x - m.x, m.x);
    o.y = fmaf(gw, v.y - m.y, m.y);
    o.z = fmaf(gw, v.z - m.z, m.z);
    o.w = fmaf(gw, v.w - m.w, m.w);
    reinterpret_cast<float4*>(out)[idx] = o;
}

// cat[b, 0:512] = refined[b,:], cat[b, 512:544] = remap[b,:]
__global__ void concat_kernel(const float* __restrict__ refined,
                              const float* __restrict__ remap,
                              float* __restrict__ cat) {
    int idx = blockIdx.x * blockDim.x + threadIdx.x;
    if (idx >= BATCH * CATK) return;
    int b = idx / CATK, c = idx - b * CATK;
    cat[idx] = (c < EDGE) ? refined[(size_t)b * EDGE + c]
                          : remap[(size_t)b * GRP + (c - EDGE)];
}

// P = exp(base_map), elementwise
__global__ void expP_kernel(const float* __restrict__ base_map,
                            float* __restrict__ P) {
    int idx = blockIdx.x * blockDim.x + threadIdx.x;
    P[idx] = expf(base_map[idx]);
}

// UV[b,:]     = exp(adapt[b,:] - rowmax)
// UV[512+b,:] = exp(adapt[b,:] - rowmax) * refined[b,:]
__global__ void uv_kernel(const float* __restrict__ adapt,
                          const float* __restrict__ refined,
                          float* __restrict__ UV) {
    int b = blockIdx.x;
    int e = threadIdx.x;          // 512 threads
    float x = adapt[(size_t)b * EDGE + e];
    float m = blockReduceMax(x);
    float u = expf(x - m);
    UV[(size_t)b * EDGE + e] = u;
    UV[(size_t)(BATCH + b) * EDGE + e] = u * refined[(size_t)b * EDGE + e];
}

// io[b,c] = R[512+b,c] / R[b,c]
__global__ void io_kernel(const float* __restrict__ R,
                          float* __restrict__ io) {
    int idx = blockIdx.x * blockDim.x + threadIdx.x;
    int b = idx >> 8, c = idx & 255;
    io[idx] = R[(size_t)(BATCH + b) * IOC + c] / R[(size_t)b * IOC + c];
}

// ---------------------------------------------------------------------------
static inline void gemm_tc(const float* A, const float* W, const float* bias,
                           const float* addend, float* C,
                           int M, int N, int K, int act) {
    dim3 grid(N / 64, M / 64);
    if (act == 0)      gemm_tf32_kernel<0><<<grid, 128>>>(A, W, bias, addend, C, M, N, K);
    else if (act == 1) gemm_tf32_kernel<1><<<grid, 128>>>(A, W, bias, addend, C, M, N, K);
    else               gemm_tf32_kernel<2><<<grid, 128>>>(A, W, bias, addend, C, M, N, K);
}

extern "C" void kernel_launch(void* const* d_in, const int* in_sizes, int n_in,
                              void* d_out, int out_size) {
    const float* signal     = (const float*)d_in[0];
    const float* memory     = (const float*)d_in[1];
    const float* remap_code = (const float*)d_in[2];
    const float* enc_w1     = (const float*)d_in[3];
    const float* enc_b1     = (const float*)d_in[4];
    const float* enc_w2     = (const float*)d_in[5];
    const float* enc_b2     = (const float*)d_in[6];
    const float* edge_w     = (const float*)d_in[7];
    const float* edge_b     = (const float*)d_in[8];
    const float* energy_w   = (const float*)d_in[9];
    const float* energy_b   = (const float*)d_in[10];
    const float* rq_w       = (const float*)d_in[11];
    const float* rq_b       = (const float*)d_in[12];
    const float* wg_w       = (const float*)d_in[13];
    const float* wg_b       = (const float*)d_in[14];
    const float* wv_w       = (const float*)d_in[15];
    const float* wv_b       = (const float*)d_in[16];
    const float* memory_key = (const float*)d_in[17];
    const float* m2e_w      = (const float*)d_in[18];
    const float* m2e_b      = (const float*)d_in[19];
    const float* base_map   = (const float*)d_in[20];
    const float* a1_w       = (const float*)d_in[21];
    const float* a1_b       = (const float*)d_in[22];
    const float* a2_w       = (const float*)d_in[23];
    const float* a2_b       = (const float*)d_in[24];

    float* out = (float*)d_out;
    float* o_latent  = out + OUT_LATENT;
    float* o_refined = out + OUT_REFINED;
    float* o_energy  = out + OUT_ENERGY;
    float* o_io      = out + OUT_IO;
    float* o_newmem  = out + OUT_NEWMEM;
    float* o_weights = out + OUT_WEIGHTS;

    float* scratch = nullptr;
    cudaGetSymbolAddress((void**)&scratch, g_scratch);
    float* lat1      = scratch + OFF_LAT1;
    float* readiness = scratch + OFF_READY;
    float* query     = scratch + OFF_QUERY;
    float* logits    = scratch + OFF_LOGITS;
    float* value     = scratch + OFF_VALUE;
    float* readv     = scratch + OFF_READ;
    float* gate      = scratch + OFF_GATE;
    float* cat       = scratch + OFF_CAT;
    float* hmid      = scratch + OFF_H;
    float* adapt     = scratch + OFF_ADAPT;
    float* UV        = scratch + OFF_UV;
    float* P         = scratch + OFF_P;
    float* R         = scratch + OFF_R;

    // 1-2: encoder
    gemm_tc(signal, enc_w1, enc_b1, nullptr, lat1,     BATCH, HID, SIG, 1);
    gemm_tc(lat1,   enc_w2, enc_b2, nullptr, o_latent, BATCH, HID, HID, 1);

    // 3: readiness (pre-refined), 4: energy
    gemm_tc(o_latent, edge_w, edge_b, nullptr, readiness, BATCH, EDGE, HID, 2);
    energy_kernel<<<BATCH, 256>>>(o_latent, energy_w, energy_b, o_energy);

    // 5-7: query -> logits -> softmax weights
    gemm_tc(o_latent, rq_w, rq_b, nullptr, query, BATCH, MEM, HID, 0);
    gemm_tc(query, memory_key, nullptr, nullptr, logits, BATCH, SLOTS, MEM, 0);
    softmax256_kernel<<<BATCH, 256>>>(logits, o_weights);

    // 8: read, 9: gate, 10: value, 11: new_memory
    read_kernel<<<BATCH, 128>>>(o_weights, memory, readv);
    gate_kernel<<<BATCH, 256>>>(o_latent, readv, wg_w, wg_b, gate);
    gemm_tc(o_latent, wv_w, wv_b, nullptr, value, BATCH, MEM, HID, 0);
    newmem_kernel<<<(BATCH*SLOTS*MEM/4)/256, 256>>>(memory, o_weights, gate, value, o_newmem);

    // 12: refined = sigmoid(readiness + read@m2e^T + m2e_b)
    gemm_tc(readv, m2e_w, m2e_b, readiness, o_refined, BATCH, EDGE, MEM, 2);

    // 13-15: router MLP
    concat_kernel<<<(BATCH*CATK + 255)/256, 256>>>(o_refined, remap_code, cat);
    gemm_tc(cat,  a1_w, a1_b, nullptr, hmid,  BATCH, EDGE, CATK, 1);
    gemm_tc(hmid, a2_w, a2_b, nullptr, adapt, BATCH, EDGE, EDGE, 0);

    // 16-19: factorized io softmax: two small GEMMs instead of [B,IOC,EDGE] softmax
    expP_kernel<<<(IOC*EDGE)/256, 256>>>(base_map, P);
    uv_kernel<<<BATCH, EDGE>>>(adapt, o_refined, UV);
    gemm_tc(UV, P, nullptr, nullptr, R, 2*BATCH, IOC, EDGE, 0);
    io_kernel<<<(BATCH*IOC)/256, 256>>>(R, o_io);
}

// round 6
// speedup vs baseline: 1.7132x; 1.7132x over previous
#include <cuda_runtime.h>
#include <math.h>

// Shapes
#define BATCH 512
#define SIG   512
#define HID   1024
#define EDGE  512
#define SLOTS 256
#define MEM   512
#define IOC   256
#define GRP   32
#define CATK  (EDGE + GRP)   // 544

// ---------------- scratch (single __device__ symbol, offsets in floats) ----
#define OFF_LAT1   0
#define OFF_READY  524288
#define OFF_QUERY  786432
#define OFF_LOGITS 1048576
#define OFF_VALUE  1179648
#define OFF_READ   1441792
#define OFF_GATE   1703936
#define OFF_CAT    1704448
#define OFF_H      1982976
#define OFF_ADAPT  2245120
#define OFF_UV     2507264
#define OFF_P      3031552
#define OFF_R      3162624
#define OFF_PART   3424768            // 1,048,576 floats of split-K partials
#define SCRATCH_FLOATS (OFF_PART + 1048576)

__device__ float g_scratch[SCRATCH_FLOATS];

// Output layout (flat concat, reference return order)
#define OUT_LATENT  0
#define OUT_REFINED 524288
#define OUT_ENERGY  786432
#define OUT_IO      786944
#define OUT_NEWMEM  918016
#define OUT_WEIGHTS 68026880

// ---------------------------------------------------------------------------
__device__ __forceinline__ float sigmoidf_(float x) { return 1.0f / (1.0f + expf(-x)); }
__device__ __forceinline__ float siluf_(float x)    { return x / (1.0f + expf(-x)); }

__device__ __forceinline__ float blockReduceSum(float v) {
    __shared__ float sh[33];
    __syncthreads();
    int lane = threadIdx.x & 31, wid = threadIdx.x >> 5;
    #pragma unroll
    for (int o = 16; o > 0; o >>= 1) v += __shfl_down_sync(0xffffffffu, v, o);
    if (lane == 0) sh[wid] = v;
    __syncthreads();
    int nw = (blockDim.x + 31) >> 5;
    if (wid == 0) {
        float w = (lane < nw) ? sh[lane] : 0.0f;
        #pragma unroll
        for (int o = 16; o > 0; o >>= 1) w += __shfl_down_sync(0xffffffffu, w, o);
        if (lane == 0) sh[32] = w;
    }
    __syncthreads();
    return sh[32];
}

__device__ __forceinline__ float blockReduceMax(float v) {
    __shared__ float sh[33];
    __syncthreads();
    int lane = threadIdx.x & 31, wid = threadIdx.x >> 5;
    #pragma unroll
    for (int o = 16; o > 0; o >>= 1) v = fmaxf(v, __shfl_down_sync(0xffffffffu, v, o));
    if (lane == 0) sh[wid] = v;
    __syncthreads();
    int nw = (blockDim.x + 31) >> 5;
    if (wid == 0) {
        float w = (lane < nw) ? sh[lane] : -3.4e38f;
        #pragma unroll
        for (int o = 16; o > 0; o >>= 1) w = fmaxf(w, __shfl_down_sync(0xffffffffu, w, o));
        if (lane == 0) sh[32] = w;
    }
    __syncthreads();
    return sh[32];
}

// ---------------------------------------------------------------------------
// 3xTF32 split-K tensor-core GEMM partials:
//   part[z][M,N] += A[M,Kslice] @ W[N,Kslice]^T
// BM=BN=64, BK=16, 256 threads (8 warps, each 32x16 = 2x2 m16n8k8 atoms).
// fp32 accuracy via hi/lo tf32 split: hi*hi + hi*lo + lo*hi (pass-reordered
// so each accumulator has dependency distance 4).
__device__ __forceinline__ unsigned f2tf32(float f) {
    unsigned u;
    asm("cvt.rna.tf32.f32 %0, %1;" : "=r"(u) : "f"(f));
    return u;
}

__device__ __forceinline__ void mma_tf32(float c[4], const unsigned a[4], const unsigned b[2]) {
    asm("mma.sync.aligned.m16n8k8.row.col.f32.tf32.tf32.f32 "
        "{%0,%1,%2,%3}, {%4,%5,%6,%7}, {%8,%9}, {%0,%1,%2,%3};\n"
        : "+f"(c[0]), "+f"(c[1]), "+f"(c[2]), "+f"(c[3])
        : "r"(a[0]), "r"(a[1]), "r"(a[2]), "r"(a[3]), "r"(b[0]), "r"(b[1]));
}

#define SMPITCH 20   // bank-conflict-free pitch (20r+c distinct banks over a warp)

__global__ void __launch_bounds__(256, 2)
gemm_tf32_part_kernel(const float* __restrict__ A,
                      const float* __restrict__ W,
                      float* __restrict__ Cpart,
                      int M, int N, int K, int kChunk) {
    __shared__ float Ah[64][SMPITCH];
    __shared__ float Al[64][SMPITCH];
    __shared__ float Bh[64][SMPITCH];
    __shared__ float Bl[64][SMPITCH];

    const int bx = blockIdx.x;           // N tile
    const int by = blockIdx.y;           // M tile
    const int bz = blockIdx.z;           // K split
    const int tid = threadIdx.x;
    const int lane = tid & 31;
    const int warp = tid >> 5;
    const int wm = (warp >> 2) << 5;     // 0 or 32
    const int wn = (warp & 3) << 4;      // 0,16,32,48

    // staging: thread owns one float4 of the 64x16 tile
    const int trow = tid >> 2;           // 0..63
    const int tkof = (tid & 3) << 2;     // 0,4,8,12

    const int kStart = bz * kChunk;
    const float* Aptr = A + (size_t)(by * 64 + trow) * K + kStart + tkof;
    const float* Wptr = W + (size_t)(bx * 64 + trow) * K + kStart + tkof;

    float c[2][2][4];
    #pragma unroll
    for (int mi = 0; mi < 2; mi++)
        #pragma unroll
        for (int ni = 0; ni < 2; ni++)
            #pragma unroll
            for (int r = 0; r < 4; r++) c[mi][ni][r] = 0.0f;

    float4 av = *reinterpret_cast<const float4*>(Aptr);
    float4 wv = *reinterpret_cast<const float4*>(Wptr);

    const int r4 = lane >> 2;            // 0..7
    const int c4 = lane & 3;             // 0..3

    for (int kt = 0; kt < kChunk; kt += 16) {
        // convert + stage current tile (float4 smem stores, 16B aligned)
        {
            float va[4] = {av.x, av.y, av.z, av.w};
            float vw[4] = {wv.x, wv.y, wv.z, wv.w};
            float ah4[4], al4[4], bh4[4], bl4[4];
            #pragma unroll
            for (int i = 0; i < 4; i++) {
                float ahf = __uint_as_float(f2tf32(va[i]));
                ah4[i] = ahf;
                al4[i] = __uint_as_float(f2tf32(va[i] - ahf));
                float bhf = __uint_as_float(f2tf32(vw[i]));
                bh4[i] = bhf;
                bl4[i] = __uint_as_float(f2tf32(vw[i] - bhf));
            }
            *reinterpret_cast<float4*>(&Ah[trow][tkof]) = make_float4(ah4[0], ah4[1], ah4[2], ah4[3]);
            *reinterpret_cast<float4*>(&Al[trow][tkof]) = make_float4(al4[0], al4[1], al4[2], al4[3]);
            *reinterpret_cast<float4*>(&Bh[trow][tkof]) = make_float4(bh4[0], bh4[1], bh4[2], bh4[3]);
            *reinterpret_cast<float4*>(&Bl[trow][tkof]) = make_float4(bl4[0], bl4[1], bl4[2], bl4[3]);
        }
        __syncthreads();

        if (kt + 16 < kChunk) {          // prefetch next tile
            av = *reinterpret_cast<const float4*>(Aptr + kt + 16);
            wv = *reinterpret_cast<const float4*>(Wptr + kt + 16);
        }

        #pragma unroll
        for (int ks = 0; ks < 16; ks += 8) {
            unsigned ah[2][4], al[2][4], bh[2][2], bl[2][2];
            #pragma unroll
            for (int mi = 0; mi < 2; mi++) {
                int mb = wm + mi * 16;
                ah[mi][0] = __float_as_uint(Ah[mb + r4    ][ks + c4    ]);
                ah[mi][1] = __float_as_uint(Ah[mb + r4 + 8][ks + c4    ]);
                ah[mi][2] = __float_as_uint(Ah[mb + r4    ][ks + c4 + 4]);
                ah[mi][3] = __float_as_uint(Ah[mb + r4 + 8][ks + c4 + 4]);
                al[mi][0] = __float_as_uint(Al[mb + r4    ][ks + c4    ]);
                al[mi][1] = __float_as_uint(Al[mb + r4 + 8][ks + c4    ]);
                al[mi][2] = __float_as_uint(Al[mb + r4    ][ks + c4 + 4]);
                al[mi][3] = __float_as_uint(Al[mb + r4 + 8][ks + c4 + 4]);
            }
            #pragma unroll
            for (int ni = 0; ni < 2; ni++) {
                int nb = wn + ni * 8 + r4;
                bh[ni][0] = __float_as_uint(Bh[nb][ks + c4    ]);
                bh[ni][1] = __float_as_uint(Bh[nb][ks + c4 + 4]);
                bl[ni][0] = __float_as_uint(Bl[nb][ks + c4    ]);
                bl[ni][1] = __float_as_uint(Bl[nb][ks + c4 + 4]);
            }
            // pass-reordered: 4 independent accumulators per pass
            #pragma unroll
            for (int mi = 0; mi < 2; mi++)
                #pragma unroll
                for (int ni = 0; ni < 2; ni++)
                    mma_tf32(c[mi][ni], ah[mi], bh[ni]);
            #pragma unroll
            for (int mi = 0; mi < 2; mi++)
                #pragma unroll
                for (int ni = 0; ni < 2; ni++)
                    mma_tf32(c[mi][ni], ah[mi], bl[ni]);
            #pragma unroll
            for (int mi = 0; mi < 2; mi++)
                #pragma unroll
                for (int ni = 0; ni < 2; ni++)
                    mma_tf32(c[mi][ni], al[mi], bh[ni]);
        }
        __syncthreads();
    }

    // write partials
    float* Cp = Cpart + (size_t)bz * M * N;
    #pragma unroll
    for (int mi = 0; mi < 2; mi++) {
        #pragma unroll
        for (int ni = 0; ni < 2; ni++) {
            int col0 = bx * 64 + wn + ni * 8 + c4 * 2;
            #pragma unroll
            for (int half = 0; half < 2; half++) {
                int row = by * 64 + wm + mi * 16 + r4 + half * 8;
                *reinterpret_cast<float2*>(Cp + (size_t)row * N + col0) =
                    make_float2(c[mi][ni][half * 2 + 0], c[mi][ni][half * 2 + 1]);
            }
        }
    }
}

// Reduce split-K partials: C = act(sum_p part[p] + bias + addend), float4.
// N must be a power of two and multiple of 4.
template<int ACT>
__global__ void reduce_kernel(const float* __restrict__ part,
                              const float* __restrict__ bias,
                              const float* __restrict__ addend,
                              float* __restrict__ C,
                              int MN4, int N, int nsplit) {
    int i = blockIdx.x * blockDim.x + threadIdx.x;
    if (i >= MN4) return;
    const float4* p4 = reinterpret_cast<const float4*>(part);
    float4 s = p4[i];
    for (int p = 1; p < nsplit; p++) {
        float4 t = p4[(size_t)p * MN4 + i];
        s.x += t.x; s.y += t.y; s.z += t.z; s.w += t.w;
    }
    int col = (i & (N / 4 - 1)) << 2;
    if (bias) {
        s.x += bias[col + 0]; s.y += bias[col + 1];
        s.z += bias[col + 2]; s.w += bias[col + 3];
    }
    if (addend) {
        float4 t = reinterpret_cast<const float4*>(addend)[i];
        s.x += t.x; s.y += t.y; s.z += t.z; s.w += t.w;
    }
    if (ACT == 1) { s.x = siluf_(s.x); s.y = siluf_(s.y); s.z = siluf_(s.z); s.w = siluf_(s.w); }
    if (ACT == 2) { s.x = sigmoidf_(s.x); s.y = sigmoidf_(s.y); s.z = sigmoidf_(s.z); s.w = sigmoidf_(s.w); }
    reinterpret_cast<float4*>(C)[i] = s;
}

// ---------------------------------------------------------------------------
// Fused per-row memory block: softmax(logits) -> weights, read, gate, energy.
// One block (256 threads) per batch row.
__global__ void fused_mem_kernel(const float* __restrict__ logits,
                                 const float* __restrict__ memory,
                                 const float* __restrict__ latent,
                                 const float* __restrict__ wg,
                                 const float* __restrict__ wgb,
                                 const float* __restrict__ ew,
                                 const float* __restrict__ eb,
                                 float* __restrict__ weights_out,
                                 float* __restrict__ readv,
                                 float* __restrict__ gate,
                                 float* __restrict__ energy) {
    __shared__ float wsh[SLOTS];
    int b = blockIdx.x;
    int tid = threadIdx.x;

    // softmax over 256 slots
    float x = logits[(size_t)b * SLOTS + tid];
    float m = blockReduceMax(x);
    float e = expf(x - m);
    float ssum = blockReduceSum(e);
    float w = e / ssum;
    weights_out[(size_t)b * SLOTS + tid] = w;
    wsh[tid] = w;
    __syncthreads();

    // read: 128 threads each own one float4 of d
    float4 acc = make_float4(0.f, 0.f, 0.f, 0.f);
    if (tid < MEM / 4) {
        const float4* mb = reinterpret_cast<const float4*>(memory + (size_t)b * SLOTS * MEM);
        #pragma unroll 4
        for (int s = 0; s < SLOTS; s++) {
            float ws = wsh[s];
            float4 mv = mb[(size_t)s * (MEM / 4) + tid];
            acc.x = fmaf(ws, mv.x, acc.x);
            acc.y = fmaf(ws, mv.y, acc.y);
            acc.z = fmaf(ws, mv.z, acc.z);
            acc.w = fmaf(ws, mv.w, acc.w);
        }
        reinterpret_cast<float4*>(readv + (size_t)b * MEM)[tid] = acc;
    }

    // gate: latent·wg[0:HID] + read·wg[HID:] ; energy: latent·ew
    float g = 0.0f, en = 0.0f;
    if (tid < MEM / 4) {
        float4 wv = reinterpret_cast<const float4*>(wg + HID)[tid];
        g = acc.x * wv.x + acc.y * wv.y + acc.z * wv.z + acc.w * wv.w;
    }
    const float4* lx = reinterpret_cast<const float4*>(latent + (size_t)b * HID);
    const float4* w1 = reinterpret_cast<const float4*>(wg);
    const float4* ev = reinterpret_cast<const float4*>(ew);
    for (int i = tid; i < HID / 4; i += blockDim.x) {
        float4 xv = lx[i], gv = w1[i], eV = ev[i];
        g  += xv.x * gv.x + xv.y * gv.y + xv.z * gv.z + xv.w * gv.w;
        en += xv.x * eV.x + xv.y * eV.y + xv.z * eV.z + xv.w * eV.w;
    }
    g  = blockReduceSum(g);
    en = blockReduceSum(en);
    if (tid == 0) {
        gate[b]   = sigmoidf_(g + wgb[0]);
        energy[b] = fmaxf(en + eb[0], 0.0f);
    }
}

// new_memory[b,s,d] = m + gate[b]*w[b,s]*(value[b,d] - m), float4 over d
__global__ void newmem_kernel(const float* __restrict__ memory,
                              const float* __restrict__ weights,
                              const float* __restrict__ gate,
                              const float* __restrict__ value,
                              float* __restrict__ out) {
    size_t idx = (size_t)blockIdx.x * blockDim.x + threadIdx.x;  // float4 index
    int b   = (int)(idx >> 15);           // SLOTS*MEM/4 = 32768 per batch
    int rem = (int)(idx & 32767);
    int s   = rem >> 7;                   // MEM/4 = 128
    int d4  = rem & 127;
    float gw = gate[b] * weights[(size_t)b * SLOTS + s];
    float4 m = reinterpret_cast<const float4*>(memory)[idx];
    float4 v = reinterpret_cast<const float4*>(value)[(size_t)b * 128 + d4];
    float4 o;
    o.x = fmaf(gw, v.x - m.x, m.x);
    o.y = fmaf(gw, v.y - m.y, m.y);
    o.z = fmaf(gw, v.z - m.z, m.z);
    o.w = fmaf(gw, v.w - m.w, m.w);
    reinterpret_cast<float4*>(out)[idx] = o;
}

// cat[b, 0:512] = refined[b,:], cat[b, 512:544] = remap[b,:]
__global__ void concat_kernel(const float* __restrict__ refined,
                              const float* __restrict__ remap,
                              float* __restrict__ cat) {
    int idx = blockIdx.x * blockDim.x + threadIdx.x;
    if (idx >= BATCH * CATK) return;
    int b = idx / CATK, c = idx - b * CATK;
    cat[idx] = (c < EDGE) ? refined[(size_t)b * EDGE + c]
                          : remap[(size_t)b * GRP + (c - EDGE)];
}

// P = exp(base_map), elementwise
__global__ void expP_kernel(const float* __restrict__ base_map,
                            float* __restrict__ P) {
    int idx = blockIdx.x * blockDim.x + threadIdx.x;
    P[idx] = expf(base_map[idx]);
}

// UV[b,:]     = exp(adapt[b,:] - rowmax)
// UV[512+b,:] = exp(adapt[b,:] - rowmax) * refined[b,:]
__global__ void uv_kernel(const float* __restrict__ adapt,
                          const float* __restrict__ refined,
                          float* __restrict__ UV) {
    int b = blockIdx.x;
    int e = threadIdx.x;          // 512 threads
    float x = adapt[(size_t)b * EDGE + e];
    float m = blockReduceMax(x);
    float u = expf(x - m);
    UV[(size_t)b * EDGE + e] = u;
    UV[(size_t)(BATCH + b) * EDGE + e] = u * refined[(size_t)b * EDGE + e];
}

// io[b,c] = R[512+b,c] / R[b,c]
__global__ void io_kernel(const float* __restrict__ R,
                          float* __restrict__ io) {
    int idx = blockIdx.x * blockDim.x + threadIdx.x;
    int b = idx >> 8, c = idx & 255;
    io[idx] = R[(size_t)(BATCH + b) * IOC + c] / R[(size_t)b * IOC + c];
}

// ---------------------------------------------------------------------------
// helper: split-K tf32 GEMM + fused-epilogue reduce
static inline void gemm_tc(const float* A, const float* W, const float* bias,
                           const float* addend, float* C, float* part,
                           int M, int N, int K, int nsplit, int act) {
    int kChunk = K / nsplit;
    dim3 grid(N / 64, M / 64, nsplit);
    gemm_tf32_part_kernel<<<grid, 256>>>(A, W, part, M, N, K, kChunk);
    int MN4 = (M * N) / 4;
    int rb = (MN4 + 255) / 256;
    if (act == 0)      reduce_kernel<0><<<rb, 256>>>(part, bias, addend, C, MN4, N, nsplit);
    else if (act == 1) reduce_kernel<1><<<rb, 256>>>(part, bias, addend, C, MN4, N, nsplit);
    else               reduce_kernel<2><<<rb, 256>>>(part, bias, addend, C, MN4, N, nsplit);
}

extern "C" void kernel_launch(void* const* d_in, const int* in_sizes, int n_in,
                              void* d_out, int out_size) {
    const float* signal     = (const float*)d_in[0];
    const float* memory     = (const float*)d_in[1];
    const float* remap_code = (const float*)d_in[2];
    const float* enc_w1     = (const float*)d_in[3];
    const float* enc_b1     = (const float*)d_in[4];
    const float* enc_w2     = (const float*)d_in[5];
    const float* enc_b2     = (const float*)d_in[6];
    const float* edge_w     = (const float*)d_in[7];
    const float* edge_b     = (const float*)d_in[8];
    const float* energy_w   = (const float*)d_in[9];
    const float* energy_b   = (const float*)d_in[10];
    const float* rq_w       = (const float*)d_in[11];
    const float* rq_b       = (const float*)d_in[12];
    const float* wg_w       = (const float*)d_in[13];
    const float* wg_b       = (const float*)d_in[14];
    const float* wv_w       = (const float*)d_in[15];
    const float* wv_b       = (const float*)d_in[16];
    const float* memory_key = (const float*)d_in[17];
    const float* m2e_w      = (const float*)d_in[18];
    const float* m2e_b      = (const float*)d_in[19];
    const float* base_map   = (const float*)d_in[20];
    const float* a1_w       = (const float*)d_in[21];
    const float* a1_b       = (const float*)d_in[22];
    const float* a2_w       = (const float*)d_in[23];
    const float* a2_b       = (const float*)d_in[24];

    float* out = (float*)d_out;
    float* o_latent  = out + OUT_LATENT;
    float* o_refined = out + OUT_REFINED;
    float* o_energy  = out + OUT_ENERGY;
    float* o_io      = out + OUT_IO;
    float* o_newmem  = out + OUT_NEWMEM;
    float* o_weights = out + OUT_WEIGHTS;

    float* scratch = nullptr;
    cudaGetSymbolAddress((void**)&scratch, g_scratch);
    float* lat1      = scratch + OFF_LAT1;
    float* readiness = scratch + OFF_READY;
    float* query     = scratch + OFF_QUERY;
    float* logits    = scratch + OFF_LOGITS;
    float* value     = scratch + OFF_VALUE;
    float* readv     = scratch + OFF_READ;
    float* gate      = scratch + OFF_GATE;
    float* cat       = scratch + OFF_CAT;
    float* hmid      = scratch + OFF_H;
    float* adapt     = scratch + OFF_ADAPT;
    float* UV        = scratch + OFF_UV;
    float* P         = scratch + OFF_P;
    float* R         = scratch + OFF_R;
    float* part      = scratch + OFF_PART;

    // 1-2: encoder (split-K chosen so every launch has >=256 CTAs, part <=1M floats)
    gemm_tc(signal, enc_w1, enc_b1, nullptr, lat1,     part, BATCH, HID, SIG, 2, 1);
    gemm_tc(lat1,   enc_w2, enc_b2, nullptr, o_latent, part, BATCH, HID, HID, 2, 1);

    // 3: readiness (pre-refined)
    gemm_tc(o_latent, edge_w, edge_b, nullptr, readiness, part, BATCH, EDGE, HID, 4, 2);

    // 5-6: query -> logits
    gemm_tc(o_latent, rq_w, rq_b, nullptr, query, part, BATCH, MEM, HID, 4, 0);
    gemm_tc(query, memory_key, nullptr, nullptr, logits, part, BATCH, SLOTS, MEM, 8, 0);

    // 7-9 + energy: fused softmax/read/gate/energy
    fused_mem_kernel<<<BATCH, 256>>>(logits, memory, o_latent, wg_w, wg_b,
                                     energy_w, energy_b,
                                     o_weights, readv, gate, o_energy);

    // 10-11: value, new_memory
    gemm_tc(o_latent, wv_w, wv_b, nullptr, value, part, BATCH, MEM, HID, 4, 0);
    newmem_kernel<<<(BATCH*SLOTS*MEM/4)/256, 256>>>(memory, o_weights, gate, value, o_newmem);

    // 12: refined = sigmoid(readiness + read@m2e^T + m2e_b)
    gemm_tc(readv, m2e_w, m2e_b, readiness, o_refined, part, BATCH, EDGE, MEM, 4, 2);

    // 13-15: router MLP
    concat_kernel<<<(BATCH*CATK + 255)/256, 256>>>(o_refined, remap_code, cat);
    gemm_tc(cat,  a1_w, a1_b, nullptr, hmid,  part, BATCH, EDGE, CATK, 2, 1);  // K=544 -> 2x272
    gemm_tc(hmid, a2_w, a2_b, nullptr, adapt, part, BATCH, EDGE, EDGE, 4, 0);

    // 16-19: factorized io softmax
    expP_kernel<<<(IOC*EDGE)/256, 256>>>(base_map, P);
    uv_kernel<<<BATCH, EDGE>>>(adapt, o_refined, UV);
    gemm_tc(UV, P, nullptr, nullptr, R, part, 2*BATCH, IOC, EDGE, 4, 0);
    io_kernel<<<(BATCH*IOC)/256, 256>>>(R, o_io);
}